// round 7
// baseline (speedup 1.0000x reference)
#include <cuda_runtime.h>
#include <cuda_bf16.h>
#include <cstdint>

// ---------------------------------------------------------------------------
// Problem constants
// ---------------------------------------------------------------------------
#define H 64
#define NNODES 40000
#define NE 60000
#define NC5 30000
#define NC6 25000
#define E_ROWS (2 * NE)      // 120000
#define C5_ROWS (5 * NC5)    // 150000
#define C6_ROWS (6 * NC6)    // 150000
#define EPS 1e-5f

// padded row counts (GEMM stores are unguarded)
#define PAD_N  40064
#define PAD_R  30080
#define PAD_F  150016

#define EPI_PLAIN 0
#define EPI_STATS 1

// ---------------------------------------------------------------------------
// Device scratch
// ---------------------------------------------------------------------------
__device__ float g_node64[NNODES * 66];   // [0:64*N) node64, then cnt5, cnt6
__device__ float g_b1_5[NC5 * 64];
__device__ float g_b1_6[NC6 * 64];
__device__ float g_n128_5[NNODES * 128];
__device__ float g_n128_6[NNODES * 128];
__device__ float g_b2_5[NC5 * 128];
__device__ float g_b2_6[NC6 * 128];
__device__ float g_nodeS[NNODES * 320];
__device__ float g_B[PAD_N * 128];
__device__ float g_Bm[PAD_N * 128];
__device__ float g_P[PAD_N * 128];
__device__ float g_R[PAD_R * 128];
__device__ float g_F[PAD_F * 128];
__device__ float g_h[PAD_F * 128];
__device__ float g_z[PAD_F * 64];
__device__ float g_wE1[704 * 128];
__device__ float g_wE2[128 * 64];
__device__ float g_wC1[320 * 128];
__device__ float g_wC2[128 * 64];
__device__ float g_stats[256];            // [0:128) sum, [128:256) sumsq
__device__ float g_scale1[128];
__device__ float g_shift1[128];
__device__ float g_scale2[64];
__device__ float g_shift2[64];

// ---------------------------------------------------------------------------
// Helpers
// ---------------------------------------------------------------------------
__device__ __forceinline__ uint32_t smem_u32(const void* p) {
    uint32_t a;
    asm("{ .reg .u64 t; cvta.to.shared.u64 t, %1; cvt.u32.u64 %0, t; }"
        : "=r"(a) : "l"(p));
    return a;
}

__device__ __forceinline__ float f2tf(float x) {
    uint32_t r;
    asm("cvt.rna.tf32.f32 %0, %1;" : "=r"(r) : "f"(x));
    return __uint_as_float(r);
}

__device__ __forceinline__ uint32_t f2tf_u(float x) {
    uint32_t r;
    asm("cvt.rna.tf32.f32 %0, %1;" : "=r"(r) : "f"(x));
    return r;
}

__device__ __forceinline__ void cp16(uint32_t dst, const void* src, int nbytes) {
    asm volatile("cp.async.ca.shared.global [%0], [%1], 16, %2;"
                 :: "r"(dst), "l"(src), "r"(nbytes) : "memory");
}
__device__ __forceinline__ void cp_commit() {
    asm volatile("cp.async.commit_group;" ::: "memory");
}
__device__ __forceinline__ void cp_wait1() {
    asm volatile("cp.async.wait_group 1;" ::: "memory");
}
__device__ __forceinline__ void cp_wait0() {
    asm volatile("cp.async.wait_group 0;" ::: "memory");
}

__device__ __forceinline__ void mma_tf32(float* d, const uint32_t* a,
                                         const uint32_t* b) {
    asm volatile(
        "mma.sync.aligned.m16n8k8.row.col.f32.tf32.tf32.f32 "
        "{%0,%1,%2,%3}, {%4,%5,%6,%7}, {%8,%9}, {%0,%1,%2,%3};"
        : "+f"(d[0]), "+f"(d[1]), "+f"(d[2]), "+f"(d[3])
        : "r"(a[0]), "r"(a[1]), "r"(a[2]), "r"(a[3]), "r"(b[0]), "r"(b[1]));
}

// ---------------------------------------------------------------------------
// tf32 mma.sync GEMM. 4-warp CTAs (warp tile 32x64), cp.async.
// BM=64/BN=128 -> 2x2 warps; BM=128/BN=64 -> 4x1 warps.
// K % 32 == 0. K==64 -> single-stage barrier-light path.
// A rows OOB -> zfill. C rows must be padded to BM multiple.
// APPLY_IN: a' = relu(a*inScale[k]+inShift[k]) (K<=128).
// EPI_STATS: column sum/sumsq of valid C rows -> stats[0:BN), stats[128:128+BN)
// ---------------------------------------------------------------------------
template <int BM, int BN, bool APPLY_IN, int EPI>
__global__ void __launch_bounds__(32 * (BM / 32) * (BN / 64))
gemm_mma(const float* __restrict__ A, const float* __restrict__ B,
         float* __restrict__ C, int M, int K,
         const float* __restrict__ inScale,
         const float* __restrict__ inShift,
         float* __restrict__ stats) {
    constexpr int WM = BM / 32, WN = BN / 64;
    constexpr int THREADS = 32 * WM * WN;
    constexpr int BK = 32, APAD = 36, BPAD = BN + 8;
    constexpr int ASZ = BM * APAD, BSZ = BK * BPAD, STG = ASZ + BSZ;
    constexpr int SOFF = 256;
    constexpr int NT = 8;  // 8 n-subtiles of 8 = 64 cols per warp
    constexpr int AI = BM * 8 / THREADS;
    constexpr int BI = 8 * BN / THREADS;

    extern __shared__ float sm[];
    const int tid = threadIdx.x;
    const int warp = tid >> 5, lane = tid & 31;
    const int qr = lane >> 2, ql = lane & 3;
    const int wm = warp % WM, wn = warp / WM;
    const int mBase = blockIdx.x * BM;
    const uint32_t smBase = smem_u32(sm);

    if (APPLY_IN && tid < 128) {
        sm[tid] = tid < K ? inScale[tid] : 0.f;
        sm[128 + tid] = tid < K ? inShift[tid] : 0.f;
    }

    auto issue = [&](int s, int k0) {
        const int so = SOFF + s * STG;
#pragma unroll
        for (int j = 0; j < AI; j++) {
            int i = tid + THREADS * j;
            int row = i >> 3, ch = i & 7;
            int gr = mBase + row;
            bool ok = gr < M;
            const float* src = A + (size_t)(ok ? gr : 0) * K + k0 + ch * 4;
            uint32_t dst = smBase + (uint32_t)(so + row * APAD + ch * 4) * 4;
            cp16(dst, src, ok ? 16 : 0);
        }
#pragma unroll
        for (int j = 0; j < BI; j++) {
            int i = tid + THREADS * j;
            int row = i / (BN / 4), c = i % (BN / 4);
            const float* src = B + (size_t)(k0 + row) * BN + c * 4;
            uint32_t dst =
                smBase + (uint32_t)(so + ASZ + row * BPAD + c * 4) * 4;
            cp16(dst, src, 16);
        }
    };

    float acc[2][NT][4];
#pragma unroll
    for (int t = 0; t < 2; t++)
#pragma unroll
        for (int j = 0; j < NT; j++)
#pragma unroll
            for (int r = 0; r < 4; r++) acc[t][j][r] = 0.f;

    auto do_chunk = [&](int buf, int c) {
        const float* Asm = sm + SOFF + buf * STG;
        const uint32_t* Bsm = reinterpret_cast<const uint32_t*>(Asm) + ASZ;
#pragma unroll
        for (int ks = 0; ks < 4; ks++) {
            const int k = ks * 8;
            float s0 = 1.f, h0 = 0.f, s4 = 1.f, h4 = 0.f;
            if (APPLY_IN) {
                int kc = c * 32 + k + ql;
                s0 = sm[kc];
                h0 = sm[128 + kc];
                s4 = sm[kc + 4];
                h4 = sm[128 + kc + 4];
            }
            uint32_t a[2][4];
#pragma unroll
            for (int t = 0; t < 2; t++) {
                const float* p = Asm + (wm * 32 + t * 16 + qr) * APAD + k + ql;
                float v0 = p[0], v1 = p[8 * APAD], v2 = p[4],
                      v3 = p[8 * APAD + 4];
                if (APPLY_IN) {
                    v0 = fmaxf(fmaf(v0, s0, h0), 0.f);
                    v1 = fmaxf(fmaf(v1, s0, h0), 0.f);
                    v2 = fmaxf(fmaf(v2, s4, h4), 0.f);
                    v3 = fmaxf(fmaf(v3, s4, h4), 0.f);
                }
                a[t][0] = f2tf_u(v0);
                a[t][1] = f2tf_u(v1);
                a[t][2] = f2tf_u(v2);
                a[t][3] = f2tf_u(v3);
            }
            uint32_t b[NT][2];
#pragma unroll
            for (int j = 0; j < NT; j++) {
                const uint32_t* p =
                    Bsm + (k + ql) * BPAD + wn * 64 + j * 8 + qr;
                b[j][0] = p[0];
                b[j][1] = p[4 * BPAD];
            }
#pragma unroll
            for (int t = 0; t < 2; t++)
#pragma unroll
                for (int j = 0; j < NT; j++) mma_tf32(acc[t][j], a[t], b[j]);
        }
    };

    const int nCh = K / BK;
    if (nCh == 2) {
        // short-K fast path: both chunks up front, one barrier
        issue(0, 0);
        issue(1, BK);
        cp_commit();
        cp_wait0();
        __syncthreads();
        do_chunk(0, 0);
        do_chunk(1, 1);
    } else {
        issue(0, 0);
        cp_commit();
        for (int c = 0; c < nCh; c++) {
            if (c + 1 < nCh) issue((c + 1) & 1, (c + 1) * BK);
            cp_commit();
            cp_wait1();
            __syncthreads();
            do_chunk(c & 1, c);
            __syncthreads();
        }
    }

    // ------------------ epilogue ------------------
    float ps[2 * NT], pq[2 * NT];
    if (EPI == EPI_STATS) {
#pragma unroll
        for (int i = 0; i < 2 * NT; i++) { ps[i] = 0.f; pq[i] = 0.f; }
    }

#pragma unroll
    for (int t = 0; t < 2; t++) {
#pragma unroll
        for (int rr = 0; rr < 2; rr++) {
            int row = mBase + wm * 32 + t * 16 + 8 * rr + qr;
            bool valid = row < M;
#pragma unroll
            for (int j = 0; j < NT; j++) {
                int n0 = wn * 64 + j * 8 + 2 * ql;
                float v0 = acc[t][j][2 * rr];
                float v1 = acc[t][j][2 * rr + 1];
                *reinterpret_cast<float2*>(&C[(size_t)row * BN + n0]) =
                    make_float2(v0, v1);
                if (EPI == EPI_STATS && valid) {
                    ps[2 * j] += v0;
                    pq[2 * j] += v0 * v0;
                    ps[2 * j + 1] += v1;
                    pq[2 * j + 1] += v1 * v1;
                }
            }
        }
    }

    if (EPI == EPI_STATS) {
        __syncthreads();
        for (int i = tid; i < 2 * BN; i += THREADS) sm[i] = 0.f;
        __syncthreads();
#pragma unroll
        for (int j = 0; j < NT; j++) {
            int n0 = wn * 64 + j * 8 + 2 * ql;
            atomicAdd(&sm[n0], ps[2 * j]);
            atomicAdd(&sm[n0 + 1], ps[2 * j + 1]);
            atomicAdd(&sm[BN + n0], pq[2 * j]);
            atomicAdd(&sm[BN + n0 + 1], pq[2 * j + 1]);
        }
        __syncthreads();
        if (tid < BN) {
            atomicAdd(&stats[tid], sm[tid]);
            atomicAdd(&stats[128 + tid], sm[BN + tid]);
        }
    }
}

// ---------------------------------------------------------------------------
// Memory-phase kernels
// ---------------------------------------------------------------------------
__global__ void zero_kernel(float* __restrict__ p, size_t n) {
    size_t i = (size_t)blockIdx.x * blockDim.x + threadIdx.x;
    if (i < n) p[i] = 0.f;
}

__global__ void count_atoms(const int* __restrict__ atoms,
                            float* __restrict__ cnt, int rows) {
    int i = blockIdx.x * blockDim.x + threadIdx.x;
    if (i < rows) atomicAdd(&cnt[atoms[i]], 1.f);
}

__global__ void scatter_add4(const float* __restrict__ src,
                             const int* __restrict__ atoms,
                             float* __restrict__ node, int rows, int C) {
    int C4 = C >> 2;
    int idx = blockIdx.x * blockDim.x + threadIdx.x;
    if (idx >= rows * C4) return;
    int r = idx / C4;
    int c = (idx - r * C4) << 2;
    float4 v = *reinterpret_cast<const float4*>(&src[(size_t)r * C + c]);
    float* dst = &node[(size_t)atoms[r] * C + c];
    atomicAdd(dst + 0, v.x);
    atomicAdd(dst + 1, v.y);
    atomicAdd(dst + 2, v.z);
    atomicAdd(dst + 3, v.w);
}

template <int G>
__global__ void bc_gather(const float* __restrict__ node,
                          const int* __restrict__ atoms,
                          float* __restrict__ out, int nCyc, int C) {
    int idx = blockIdx.x * blockDim.x + threadIdx.x;
    if (idx >= nCyc * C) return;
    int i = idx / C;
    int c = idx - i * C;
    float s = 0.f;
#pragma unroll
    for (int k = 0; k < G; k++) s += node[(size_t)atoms[i * G + k] * C + c];
    out[(size_t)i * C + c] = s;
}

__global__ void init_node128(const float* __restrict__ node64,
                             const float* __restrict__ cnt,
                             float* __restrict__ node128) {
    int idx = blockIdx.x * blockDim.x + threadIdx.x;
    if (idx >= NNODES * 64) return;
    int a = idx >> 6, c = idx & 63;
    float s = cnt[a];
    node128[(size_t)a * 128 + c] = s * node64[(size_t)a * 64 + c];
    node128[(size_t)a * 128 + 64 + c] = 0.f;
}

__global__ void init_nodeS(const float* __restrict__ n5,
                           const float* __restrict__ n6,
                           const float* __restrict__ c5,
                           const float* __restrict__ c6,
                           float* __restrict__ nodeS) {
    int idx = blockIdx.x * blockDim.x + threadIdx.x;
    if (idx >= NNODES * 320) return;
    int a = idx / 320, c = idx - a * 320;
    float v = 0.f;
    if (c < 128)
        v = c5[a] * n5[(size_t)a * 128 + c] + c6[a] * n6[(size_t)a * 128 + c];
    nodeS[idx] = v;
}

template <int G>
__global__ void scatter_grp4(const float* __restrict__ src,
                             const int* __restrict__ atoms,
                             float* __restrict__ dst, int rows, int C,
                             int pitch, int off) {
    int C4 = C >> 2;
    int idx = blockIdx.x * blockDim.x + threadIdx.x;
    if (idx >= rows * C4) return;
    int r = idx / C4;
    int c = (idx - r * C4) << 2;
    float4 v =
        *reinterpret_cast<const float4*>(&src[(size_t)(r / G) * C + c]);
    float* d = &dst[(size_t)atoms[r] * pitch + off + c];
    atomicAdd(d + 0, v.x);
    atomicAdd(d + 1, v.y);
    atomicAdd(d + 2, v.z);
    atomicAdd(d + 3, v.w);
}

__global__ void round_tf32(const float* __restrict__ src,
                           float* __restrict__ dst, int n) {
    int i = blockIdx.x * blockDim.x + threadIdx.x;
    if (i < n) dst[i] = f2tf(src[i]);
}

// edge compose: h[r] = F[r] + B[self] + Bm[a0] + Bm[a1]; fused stats
__global__ void compose_edge(const float* __restrict__ F,
                             const float* __restrict__ B,
                             const float* __restrict__ Bm,
                             const int* __restrict__ atoms,
                             float* __restrict__ h,
                             float* __restrict__ stats) {
    int c = threadIdx.x;  // 128
    float s = 0.f, q = 0.f;
    for (int r = blockIdx.x; r < E_ROWS; r += gridDim.x) {
        int e = r >> 1;
        int a0 = atoms[2 * e], a1 = atoms[2 * e + 1];
        int self = (r & 1) ? a1 : a0;
        float v = F[(size_t)r * 128 + c] + B[(size_t)self * 128 + c] +
                  Bm[(size_t)a0 * 128 + c] + Bm[(size_t)a1 * 128 + c];
        h[(size_t)r * 128 + c] = v;
        s += v;
        q += v * v;
    }
    atomicAdd(&stats[c], s);
    atomicAdd(&stats[128 + c], q);
}

// cycle compose: h[r] = F[r] + P[atoms[r]] + R[r/G]; fused stats
template <int G>
__global__ void compose_cyc(const float* __restrict__ F,
                            const float* __restrict__ P,
                            const float* __restrict__ R,
                            const int* __restrict__ atoms,
                            float* __restrict__ h, int rows,
                            float* __restrict__ stats) {
    int c = threadIdx.x;  // 128
    float s = 0.f, q = 0.f;
    for (int r = blockIdx.x; r < rows; r += gridDim.x) {
        int a = atoms[r];
        float v = F[(size_t)r * 128 + c] + P[(size_t)a * 128 + c] +
                  R[(size_t)(r / G) * 128 + c];
        h[(size_t)r * 128 + c] = v;
        s += v;
        q += v * v;
    }
    atomicAdd(&stats[c], s);
    atomicAdd(&stats[128 + c], q);
}

__global__ void make_scaleshift(const float* __restrict__ stats,
                                const float* __restrict__ g,
                                const float* __restrict__ b,
                                float* __restrict__ scale,
                                float* __restrict__ shift, int C, float invM) {
    int j = blockIdx.x * blockDim.x + threadIdx.x;
    if (j >= C) return;
    float m = stats[j] * invM;
    float v = stats[128 + j] * invM - m * m;
    v = fmaxf(v, 0.f);
    float s = g[j] * rsqrtf(v + EPS);
    scale[j] = s;
    shift[j] = b[j] - m * s;
}

__global__ void bn_relu_out(const float* __restrict__ z,
                            const float* __restrict__ scale,
                            const float* __restrict__ shift,
                            float* __restrict__ out, size_t n, int C) {
    size_t idx = (size_t)blockIdx.x * blockDim.x + threadIdx.x;
    if (idx >= n) return;
    int c = (int)(idx % C);
    out[idx] = fmaxf(z[idx] * scale[c] + shift[c], 0.f);
}

// ---------------------------------------------------------------------------
// Host orchestration
// ---------------------------------------------------------------------------
static inline int cdiv(int a, int b) { return (a + b - 1) / b; }

static float* sym_addr(const void* s) {
    void* p = nullptr;
    cudaGetSymbolAddress(&p, s);
    return (float*)p;
}

// smem sizes (floats): 256 + 2*(BM*36 + 32*(BN+8))
static const int SMEM_64_128 = (256 + 2 * (64 * 36 + 32 * 136)) * 4;   // 54272
static const int SMEM_128_64 = (256 + 2 * (128 * 36 + 32 * 72)) * 4;   // 56320

extern "C" void kernel_launch(void* const* d_in, const int* in_sizes, int n_in,
                              void* d_out, int out_size) {
    static bool attr_done = false;
    if (!attr_done) {
        cudaFuncSetAttribute(gemm_mma<64, 128, false, EPI_PLAIN>,
                             cudaFuncAttributeMaxDynamicSharedMemorySize,
                             SMEM_64_128);
        cudaFuncSetAttribute(gemm_mma<128, 64, true, EPI_STATS>,
                             cudaFuncAttributeMaxDynamicSharedMemorySize,
                             SMEM_128_64);
        attr_done = true;
    }

    const float* edge_feats = (const float*)d_in[0];
    const float* c5_feats = (const float*)d_in[1];
    const float* c6_feats = (const float*)d_in[2];
    const int* e_atoms = (const int*)d_in[3];
    const int* c5_atoms = (const int*)d_in[4];
    const int* c6_atoms = (const int*)d_in[5];
    const float* eW1 = (const float*)d_in[6];
    const float* eg1 = (const float*)d_in[7];
    const float* eb1 = (const float*)d_in[8];
    const float* eW2 = (const float*)d_in[9];
    const float* eg2 = (const float*)d_in[10];
    const float* eb2 = (const float*)d_in[11];
    const float* cW1 = (const float*)d_in[12];
    const float* cg1 = (const float*)d_in[13];
    const float* cb1 = (const float*)d_in[14];
    const float* cW2 = (const float*)d_in[15];
    const float* cg2 = (const float*)d_in[16];
    const float* cb2 = (const float*)d_in[17];

    float* out_edge = (float*)d_out;
    float* out_c5 = out_edge + (size_t)E_ROWS * H;
    float* out_c6 = out_c5 + (size_t)C5_ROWS * H;

    float* node64 = sym_addr(g_node64);
    float* cnt5 = node64 + NNODES * 64;
    float* cnt6 = node64 + NNODES * 65;
    float* b1_5 = sym_addr(g_b1_5);
    float* b1_6 = sym_addr(g_b1_6);
    float* n128_5 = sym_addr(g_n128_5);
    float* n128_6 = sym_addr(g_n128_6);
    float* b2_5 = sym_addr(g_b2_5);
    float* b2_6 = sym_addr(g_b2_6);
    float* nodeS = sym_addr(g_nodeS);
    float* Bt = sym_addr(g_B);
    float* Bm = sym_addr(g_Bm);
    float* P = sym_addr(g_P);
    float* R = sym_addr(g_R);
    float* F = sym_addr(g_F);
    float* h = sym_addr(g_h);
    float* z = sym_addr(g_z);
    float* wE1 = sym_addr(g_wE1);
    float* wE2 = sym_addr(g_wE2);
    float* wC1 = sym_addr(g_wC1);
    float* wC2 = sym_addr(g_wC2);
    float* stats = sym_addr(g_stats);
    float* sc1 = sym_addr(g_scale1);
    float* sh1 = sym_addr(g_shift1);
    float* sc2 = sym_addr(g_scale2);
    float* sh2 = sym_addr(g_shift2);

    const int TB = 256;

    // #1-3: weight rounding
    round_tf32<<<cdiv(704 * 128, TB), TB>>>(eW1, wE1, 704 * 128);
    round_tf32<<<cdiv(320 * 128, TB), TB>>>(cW1, wC1, 320 * 128);
    round_tf32<<<cdiv(128 * 64, TB), TB>>>(eW2, wE2, 128 * 64);
    // #4: edge F GEMM (profiled launch; K=64 fast path, BM=64)
    gemm_mma<64, 128, false, EPI_PLAIN><<<cdiv(E_ROWS, 64), 128, SMEM_64_128>>>(
        edge_feats, wE1, F, E_ROWS, 64, nullptr, nullptr, nullptr);
    // #5
    round_tf32<<<cdiv(128 * 64, TB), TB>>>(cW2, wC2, 128 * 64);

    // ---- scatter chain (fp32 exact) ----
    zero_kernel<<<cdiv(NNODES * 66, TB), TB>>>(node64, (size_t)NNODES * 66);
    scatter_add4<<<cdiv(E_ROWS * 16, TB), TB>>>(edge_feats, e_atoms, node64,
                                                E_ROWS, 64);
    count_atoms<<<cdiv(C5_ROWS, TB), TB>>>(c5_atoms, cnt5, C5_ROWS);
    count_atoms<<<cdiv(C6_ROWS, TB), TB>>>(c6_atoms, cnt6, C6_ROWS);

    bc_gather<5><<<cdiv(NC5 * 64, TB), TB>>>(node64, c5_atoms, b1_5, NC5, 64);
    bc_gather<6><<<cdiv(NC6 * 64, TB), TB>>>(node64, c6_atoms, b1_6, NC6, 64);

    init_node128<<<cdiv(NNODES * 64, TB), TB>>>(node64, cnt5, n128_5);
    init_node128<<<cdiv(NNODES * 64, TB), TB>>>(node64, cnt6, n128_6);
    scatter_grp4<5><<<cdiv(C5_ROWS * 16, TB), TB>>>(b1_5, c5_atoms, n128_5,
                                                    C5_ROWS, 64, 128, 64);
    scatter_grp4<6><<<cdiv(C6_ROWS * 16, TB), TB>>>(b1_6, c6_atoms, n128_6,
                                                    C6_ROWS, 64, 128, 64);

    bc_gather<5><<<cdiv(NC5 * 128, TB), TB>>>(n128_5, c5_atoms, b2_5, NC5, 128);
    bc_gather<6><<<cdiv(NC6 * 128, TB), TB>>>(n128_6, c6_atoms, b2_6, NC6, 128);

    init_nodeS<<<cdiv(NNODES * 320, TB), TB>>>(n128_5, n128_6, cnt5, cnt6,
                                               nodeS);
    scatter_grp4<5><<<cdiv(C5_ROWS * 32, TB), TB>>>(b2_5, c5_atoms, nodeS,
                                                    C5_ROWS, 128, 320, 128);
    scatter_grp4<6><<<cdiv(C6_ROWS * 32, TB), TB>>>(b2_6, c6_atoms, nodeS,
                                                    C6_ROWS, 128, 320, 128);
    scatter_grp4<1><<<cdiv(C5_ROWS * 16, TB), TB>>>(c5_feats, c5_atoms, nodeS,
                                                    C5_ROWS, 64, 320, 256);
    scatter_grp4<1><<<cdiv(C6_ROWS * 16, TB), TB>>>(c6_feats, c6_atoms, nodeS,
                                                    C6_ROWS, 64, 320, 256);

    // ================= EDGE MLP =================
    gemm_mma<64, 128, false, EPI_PLAIN><<<cdiv(NNODES, 64), 128, SMEM_64_128>>>(
        nodeS, wE1 + 64 * 128, Bt, NNODES, 320, nullptr, nullptr, nullptr);
    gemm_mma<64, 128, false, EPI_PLAIN><<<cdiv(NNODES, 64), 128, SMEM_64_128>>>(
        nodeS, wE1 + 384 * 128, Bm, NNODES, 320, nullptr, nullptr, nullptr);
    zero_kernel<<<1, 256>>>(stats, 256);
    compose_edge<<<2048, 128>>>(F, Bt, Bm, e_atoms, h, stats);
    make_scaleshift<<<1, 128>>>(stats, eg1, eb1, sc1, sh1, 128, 1.f / E_ROWS);
    zero_kernel<<<1, 256>>>(stats, 256);
    gemm_mma<128, 64, true, EPI_STATS><<<cdiv(E_ROWS, 128), 128, SMEM_128_64>>>(
        h, wE2, z, E_ROWS, 128, sc1, sh1, stats);
    make_scaleshift<<<1, 64>>>(stats, eg2, eb2, sc2, sh2, 64, 1.f / E_ROWS);
    bn_relu_out<<<cdiv(E_ROWS * 64, TB), TB>>>(z, sc2, sh2, out_edge,
                                               (size_t)E_ROWS * 64, 64);

    // ================= CYCLE5 MLP =================
    gemm_mma<64, 128, false, EPI_PLAIN><<<cdiv(C5_ROWS, 64), 128, SMEM_64_128>>>(
        c5_feats, wC1 + 256 * 128, F, C5_ROWS, 64, nullptr, nullptr, nullptr);
    gemm_mma<64, 128, false, EPI_PLAIN><<<cdiv(NNODES, 64), 128, SMEM_64_128>>>(
        n128_5, wC1, P, NNODES, 128, nullptr, nullptr, nullptr);
    gemm_mma<64, 128, false, EPI_PLAIN><<<cdiv(NC5, 64), 128, SMEM_64_128>>>(
        b2_5, wC1 + 128 * 128, R, NC5, 128, nullptr, nullptr, nullptr);
    zero_kernel<<<1, 256>>>(stats, 256);
    compose_cyc<5><<<2048, 128>>>(F, P, R, c5_atoms, h, C5_ROWS, stats);
    make_scaleshift<<<1, 128>>>(stats, cg1, cb1, sc1, sh1, 128, 1.f / C5_ROWS);
    zero_kernel<<<1, 256>>>(stats, 256);
    gemm_mma<128, 64, true, EPI_STATS><<<cdiv(C5_ROWS, 128), 128, SMEM_128_64>>>(
        h, wC2, z, C5_ROWS, 128, sc1, sh1, stats);
    make_scaleshift<<<1, 64>>>(stats, cg2, cb2, sc2, sh2, 64, 1.f / C5_ROWS);
    bn_relu_out<<<cdiv(C5_ROWS * 64, TB), TB>>>(z, sc2, sh2, out_c5,
                                                (size_t)C5_ROWS * 64, 64);

    // ================= CYCLE6 MLP =================
    gemm_mma<64, 128, false, EPI_PLAIN><<<cdiv(C6_ROWS, 64), 128, SMEM_64_128>>>(
        c6_feats, wC1 + 256 * 128, F, C6_ROWS, 64, nullptr, nullptr, nullptr);
    gemm_mma<64, 128, false, EPI_PLAIN><<<cdiv(NNODES, 64), 128, SMEM_64_128>>>(
        n128_6, wC1, P, NNODES, 128, nullptr, nullptr, nullptr);
    gemm_mma<64, 128, false, EPI_PLAIN><<<cdiv(NC6, 64), 128, SMEM_64_128>>>(
        b2_6, wC1 + 128 * 128, R, NC6, 128, nullptr, nullptr, nullptr);
    zero_kernel<<<1, 256>>>(stats, 256);
    compose_cyc<6><<<2048, 128>>>(F, P, R, c6_atoms, h, C6_ROWS, stats);
    make_scaleshift<<<1, 128>>>(stats, cg1, cb1, sc1, sh1, 128, 1.f / C6_ROWS);
    zero_kernel<<<1, 256>>>(stats, 256);
    gemm_mma<128, 64, true, EPI_STATS><<<cdiv(C6_ROWS, 128), 128, SMEM_128_64>>>(
        h, wC2, z, C6_ROWS, 128, sc1, sh1, stats);
    make_scaleshift<<<1, 64>>>(stats, cg2, cb2, sc2, sh2, 64, 1.f / C6_ROWS);
    bn_relu_out<<<cdiv(C6_ROWS * 64, TB), TB>>>(z, sc2, sh2, out_c6,
                                                (size_t)C6_ROWS * 64, 64);

    (void)in_sizes;
    (void)n_in;
    (void)out_size;
}

// round 8
// speedup vs baseline: 1.0343x; 1.0343x over previous
#include <cuda_runtime.h>
#include <cuda_bf16.h>
#include <cstdint>

// ---------------------------------------------------------------------------
// Problem constants
// ---------------------------------------------------------------------------
#define H 64
#define NNODES 40000
#define NE 60000
#define NC5 30000
#define NC6 25000
#define E_ROWS (2 * NE)      // 120000
#define C5_ROWS (5 * NC5)    // 150000
#define C6_ROWS (6 * NC6)    // 150000
#define EPS 1e-5f

// padded row counts (GEMM stores are unguarded)
#define PAD_N  40064
#define PAD_R  30080
#define PAD_F  150016

#define EPI_PLAIN 0
#define EPI_STATS 1

// ---------------------------------------------------------------------------
// Device scratch
// ---------------------------------------------------------------------------
__device__ float g_node64[NNODES * 66];   // [0:64N) node64, then cnt5, cnt6
__device__ float g_b1_5[NC5 * 64];
__device__ float g_b1_6[NC6 * 64];
__device__ float g_n128_5[NNODES * 128];
__device__ float g_n128_6[NNODES * 128];
__device__ float g_b2_5[NC5 * 128];
__device__ float g_b2_6[NC6 * 128];
__device__ float g_nodeS[NNODES * 320];
__device__ float g_B[PAD_N * 128];
__device__ float g_Bm[PAD_N * 128];
__device__ float g_P[PAD_N * 128];
__device__ float g_R[PAD_R * 128];
__device__ float g_F[PAD_F * 128];
__device__ float g_h[PAD_F * 128];
__device__ float g_z[PAD_F * 64];
__device__ float g_wE1[704 * 128];        // fragment-permuted, tf32-rounded
__device__ float g_wE2[128 * 64];
__device__ float g_wC1[320 * 128];
__device__ float g_wC2[128 * 64];
__device__ float g_stats[256];            // [0:128) sum, [128:256) sumsq
__device__ float g_scale1[128];
__device__ float g_shift1[128];
__device__ float g_scale2[64];
__device__ float g_shift2[64];

// ---------------------------------------------------------------------------
// Helpers
// ---------------------------------------------------------------------------
__device__ __forceinline__ uint32_t smem_u32(const void* p) {
    uint32_t a;
    asm("{ .reg .u64 t; cvta.to.shared.u64 t, %1; cvt.u32.u64 %0, t; }"
        : "=r"(a) : "l"(p));
    return a;
}

__device__ __forceinline__ float f2tf(float x) {
    uint32_t r;
    asm("cvt.rna.tf32.f32 %0, %1;" : "=r"(r) : "f"(x));
    return __uint_as_float(r);
}

__device__ __forceinline__ uint32_t f2tf_u(float x) {
    uint32_t r;
    asm("cvt.rna.tf32.f32 %0, %1;" : "=r"(r) : "f"(x));
    return r;
}

__device__ __forceinline__ void cp16(uint32_t dst, const void* src, int nbytes) {
    asm volatile("cp.async.ca.shared.global [%0], [%1], 16, %2;"
                 :: "r"(dst), "l"(src), "r"(nbytes) : "memory");
}
__device__ __forceinline__ void cp_commit() {
    asm volatile("cp.async.commit_group;" ::: "memory");
}
__device__ __forceinline__ void cp_wait1() {
    asm volatile("cp.async.wait_group 1;" ::: "memory");
}

__device__ __forceinline__ void mma_tf32(float* d, const uint32_t* a,
                                         const uint32_t* b) {
    asm volatile(
        "mma.sync.aligned.m16n8k8.row.col.f32.tf32.tf32.f32 "
        "{%0,%1,%2,%3}, {%4,%5,%6,%7}, {%8,%9}, {%0,%1,%2,%3};"
        : "+f"(d[0]), "+f"(d[1]), "+f"(d[2]), "+f"(d[3])
        : "r"(a[0]), "r"(a[1]), "r"(a[2]), "r"(a[3]), "r"(b[0]), "r"(b[1]));
}

// ---------------------------------------------------------------------------
// Weight permutation: W[K][N] row-major -> fragment order
//   wp[((ks*(N/8) + jn)*32 + lane)*2 + c] = tf32(W[ks*8 + (lane&3) + 4c][jn*8 + lane>>2])
// K-slice at row ko maps to float offset ko*N (same as unpermuted).
// ---------------------------------------------------------------------------
__global__ void permute_w(const float* __restrict__ W, float* __restrict__ wp,
                          int K, int N) {
    int idx = blockIdx.x * blockDim.x + threadIdx.x;
    int total = K * N;
    if (idx >= total) return;
    int pair = idx & 63;
    int lane = pair >> 1, c = pair & 1;
    int rest = idx >> 6;
    int jn = rest % (N >> 3);
    int ks = rest / (N >> 3);
    int k = ks * 8 + (lane & 3) + 4 * c;
    int n = jn * 8 + (lane >> 2);
    wp[idx] = f2tf(W[(size_t)k * N + n]);
}

// ---------------------------------------------------------------------------
// tf32 mma.sync GEMM: A via cp.async smem (double-buffered), B via direct
// LDG.64 of fragment-permuted weights (register double-buffered).
// BM=128, 256 threads, 8 warps (4 M x 2 N); warp tile 32 x BN/2.
// A:[M,K] raw fp32 (rounded in-register). C:[Mpad,BN], padded rows written.
// APPLY_IN: a' = relu(a*inScale[k]+inShift[k]) (K<=128).
// EPI_STATS: column sum/sumsq of valid rows -> stats[0:BN), stats[128:..).
// ---------------------------------------------------------------------------
template <int BN, bool APPLY_IN, int EPI>
__global__ void __launch_bounds__(256)
gemm_mma(const float* __restrict__ A, const float* __restrict__ Wp,
         float* __restrict__ C, int M, int K,
         const float* __restrict__ inScale,
         const float* __restrict__ inShift,
         float* __restrict__ stats) {
    constexpr int BM = 128, BK = 32, APAD = 36;
    constexpr int ASZ = BM * APAD;
    constexpr int SOFF = 256;
    constexpr int NT = BN / 16;          // n-subtiles per warp
    constexpr int KSF = 2 * NT * 64;     // floats per kstep block in Wp

    extern __shared__ float sm[];
    const int tid = threadIdx.x;
    const int warp = tid >> 5, lane = tid & 31;
    const int qr = lane >> 2, ql = lane & 3;
    const int wm = warp >> 1, wn = warp & 1;
    const int mBase = blockIdx.x * BM;
    const uint32_t smBase = smem_u32(sm);

    if (APPLY_IN && tid < 128) {
        sm[tid] = tid < K ? inScale[tid] : 0.f;
        sm[128 + tid] = tid < K ? inShift[tid] : 0.f;
    }

    auto issueA = [&](int s, int k0) {
        const int so = SOFF + s * ASZ;
#pragma unroll
        for (int j = 0; j < 4; j++) {
            int i = tid + 256 * j;
            int row = i >> 3, ch = i & 7;
            int gr = mBase + row;
            bool ok = gr < M;
            const float* src = A + (size_t)(ok ? gr : 0) * K + k0 + ch * 4;
            uint32_t dst = smBase + (uint32_t)(so + row * APAD + ch * 4) * 4;
            cp16(dst, src, ok ? 16 : 0);
        }
    };

    const float* wbase = Wp + (wn * NT) * 64 + lane * 2;
    float2 bf[2][NT];
    auto loadB = [&](int buf, int ksg) {
#pragma unroll
        for (int j = 0; j < NT; j++)
            bf[buf][j] = *reinterpret_cast<const float2*>(
                wbase + (size_t)ksg * KSF + j * 64);
    };

    float acc[2][NT][4];
#pragma unroll
    for (int t = 0; t < 2; t++)
#pragma unroll
        for (int j = 0; j < NT; j++)
#pragma unroll
            for (int r = 0; r < 4; r++) acc[t][j][r] = 0.f;

    const int nCh = K / BK;
    const int nKs = K / 8;
    issueA(0, 0);
    cp_commit();
    loadB(0, 0);

    for (int c = 0; c < nCh; c++) {
        if (c + 1 < nCh) issueA((c + 1) & 1, (c + 1) * BK);
        cp_commit();
        cp_wait1();
        __syncthreads();

        const float* Asm = sm + SOFF + (c & 1) * ASZ;
#pragma unroll
        for (int ks = 0; ks < 4; ks++) {
            const int ksg = c * 4 + ks;
            if (ksg + 1 < nKs) loadB((ksg + 1) & 1, ksg + 1);
            const int k = ks * 8;
            float s0 = 1.f, h0 = 0.f, s4 = 1.f, h4 = 0.f;
            if (APPLY_IN) {
                int kc = c * 32 + k + ql;
                s0 = sm[kc];
                h0 = sm[128 + kc];
                s4 = sm[kc + 4];
                h4 = sm[128 + kc + 4];
            }
            uint32_t a[2][4];
#pragma unroll
            for (int t = 0; t < 2; t++) {
                const float* p = Asm + (wm * 32 + t * 16 + qr) * APAD + k + ql;
                float v0 = p[0], v1 = p[8 * APAD], v2 = p[4],
                      v3 = p[8 * APAD + 4];
                if (APPLY_IN) {
                    v0 = fmaxf(fmaf(v0, s0, h0), 0.f);
                    v1 = fmaxf(fmaf(v1, s0, h0), 0.f);
                    v2 = fmaxf(fmaf(v2, s4, h4), 0.f);
                    v3 = fmaxf(fmaf(v3, s4, h4), 0.f);
                }
                a[t][0] = f2tf_u(v0);
                a[t][1] = f2tf_u(v1);
                a[t][2] = f2tf_u(v2);
                a[t][3] = f2tf_u(v3);
            }
            const float2* bc = bf[ksg & 1];
#pragma unroll
            for (int t = 0; t < 2; t++)
#pragma unroll
                for (int j = 0; j < NT; j++) {
                    uint32_t b2r[2] = {__float_as_uint(bc[j].x),
                                       __float_as_uint(bc[j].y)};
                    mma_tf32(acc[t][j], a[t], b2r);
                }
        }
        __syncthreads();
    }

    // ------------------ epilogue ------------------
    float ps[2 * NT], pq[2 * NT];
    if (EPI == EPI_STATS) {
#pragma unroll
        for (int i = 0; i < 2 * NT; i++) { ps[i] = 0.f; pq[i] = 0.f; }
    }

#pragma unroll
    for (int t = 0; t < 2; t++) {
#pragma unroll
        for (int rr = 0; rr < 2; rr++) {
            int row = mBase + wm * 32 + t * 16 + 8 * rr + qr;
            bool valid = row < M;
#pragma unroll
            for (int j = 0; j < NT; j++) {
                int n0 = wn * (BN / 2) + j * 8 + 2 * ql;
                float v0 = acc[t][j][2 * rr];
                float v1 = acc[t][j][2 * rr + 1];
                *reinterpret_cast<float2*>(&C[(size_t)row * BN + n0]) =
                    make_float2(v0, v1);
                if (EPI == EPI_STATS && valid) {
                    ps[2 * j] += v0;
                    pq[2 * j] += v0 * v0;
                    ps[2 * j + 1] += v1;
                    pq[2 * j + 1] += v1 * v1;
                }
            }
        }
    }

    if (EPI == EPI_STATS) {
        __syncthreads();
        for (int i = tid; i < 2 * BN; i += 256) sm[i] = 0.f;
        __syncthreads();
#pragma unroll
        for (int j = 0; j < NT; j++) {
            int n0 = wn * (BN / 2) + j * 8 + 2 * ql;
            atomicAdd(&sm[n0], ps[2 * j]);
            atomicAdd(&sm[n0 + 1], ps[2 * j + 1]);
            atomicAdd(&sm[BN + n0], pq[2 * j]);
            atomicAdd(&sm[BN + n0 + 1], pq[2 * j + 1]);
        }
        __syncthreads();
        if (tid < BN) {
            atomicAdd(&stats[tid], sm[tid]);
            atomicAdd(&stats[128 + tid], sm[BN + tid]);
        }
    }
}

// ---------------------------------------------------------------------------
// Memory-phase kernels
// ---------------------------------------------------------------------------
__global__ void zero_kernel(float* __restrict__ p, size_t n) {
    size_t i = (size_t)blockIdx.x * blockDim.x + threadIdx.x;
    if (i < n) p[i] = 0.f;
}

__global__ void count_atoms(const int* __restrict__ atoms,
                            float* __restrict__ cnt, int rows) {
    int i = blockIdx.x * blockDim.x + threadIdx.x;
    if (i < rows) atomicAdd(&cnt[atoms[i]], 1.f);
}

__global__ void scatter_add4(const float* __restrict__ src,
                             const int* __restrict__ atoms,
                             float* __restrict__ node, int rows, int C) {
    int C4 = C >> 2;
    int idx = blockIdx.x * blockDim.x + threadIdx.x;
    if (idx >= rows * C4) return;
    int r = idx / C4;
    int c = (idx - r * C4) << 2;
    float4 v = *reinterpret_cast<const float4*>(&src[(size_t)r * C + c]);
    float* dst = &node[(size_t)atoms[r] * C + c];
    atomicAdd(dst + 0, v.x);
    atomicAdd(dst + 1, v.y);
    atomicAdd(dst + 2, v.z);
    atomicAdd(dst + 3, v.w);
}

template <int G>
__global__ void bc_gather(const float* __restrict__ node,
                          const int* __restrict__ atoms,
                          float* __restrict__ out, int nCyc, int C) {
    int idx = blockIdx.x * blockDim.x + threadIdx.x;
    if (idx >= nCyc * C) return;
    int i = idx / C;
    int c = idx - i * C;
    float s = 0.f;
#pragma unroll
    for (int k = 0; k < G; k++) s += node[(size_t)atoms[i * G + k] * C + c];
    out[(size_t)i * C + c] = s;
}

__global__ void init_node128(const float* __restrict__ node64,
                             const float* __restrict__ cnt,
                             float* __restrict__ node128) {
    int idx = blockIdx.x * blockDim.x + threadIdx.x;
    if (idx >= NNODES * 64) return;
    int a = idx >> 6, c = idx & 63;
    float s = cnt[a];
    node128[(size_t)a * 128 + c] = s * node64[(size_t)a * 64 + c];
    node128[(size_t)a * 128 + 64 + c] = 0.f;
}

__global__ void init_nodeS(const float* __restrict__ n5,
                           const float* __restrict__ n6,
                           const float* __restrict__ c5,
                           const float* __restrict__ c6,
                           float* __restrict__ nodeS) {
    int idx = blockIdx.x * blockDim.x + threadIdx.x;
    if (idx >= NNODES * 320) return;
    int a = idx / 320, c = idx - a * 320;
    float v = 0.f;
    if (c < 128)
        v = c5[a] * n5[(size_t)a * 128 + c] + c6[a] * n6[(size_t)a * 128 + c];
    nodeS[idx] = v;
}

template <int G>
__global__ void scatter_grp4(const float* __restrict__ src,
                             const int* __restrict__ atoms,
                             float* __restrict__ dst, int rows, int C,
                             int pitch, int off) {
    int C4 = C >> 2;
    int idx = blockIdx.x * blockDim.x + threadIdx.x;
    if (idx >= rows * C4) return;
    int r = idx / C4;
    int c = (idx - r * C4) << 2;
    float4 v =
        *reinterpret_cast<const float4*>(&src[(size_t)(r / G) * C + c]);
    float* d = &dst[(size_t)atoms[r] * pitch + off + c];
    atomicAdd(d + 0, v.x);
    atomicAdd(d + 1, v.y);
    atomicAdd(d + 2, v.z);
    atomicAdd(d + 3, v.w);
}

// edge compose: h[r] = F[r] + B[self] + Bm[a0] + Bm[a1]; fused stats
__global__ void compose_edge(const float* __restrict__ F,
                             const float* __restrict__ B,
                             const float* __restrict__ Bm,
                             const int* __restrict__ atoms,
                             float* __restrict__ h,
                             float* __restrict__ stats) {
    int c = threadIdx.x;  // 128
    float s = 0.f, q = 0.f;
    for (int r = blockIdx.x; r < E_ROWS; r += gridDim.x) {
        int e = r >> 1;
        int a0 = atoms[2 * e], a1 = atoms[2 * e + 1];
        int self = (r & 1) ? a1 : a0;
        float v = F[(size_t)r * 128 + c] + B[(size_t)self * 128 + c] +
                  Bm[(size_t)a0 * 128 + c] + Bm[(size_t)a1 * 128 + c];
        h[(size_t)r * 128 + c] = v;
        s += v;
        q += v * v;
    }
    atomicAdd(&stats[c], s);
    atomicAdd(&stats[128 + c], q);
}

// cycle compose: h[r] = F[r] + P[atoms[r]] + R[r/G]; fused stats
template <int G>
__global__ void compose_cyc(const float* __restrict__ F,
                            const float* __restrict__ P,
                            const float* __restrict__ R,
                            const int* __restrict__ atoms,
                            float* __restrict__ h, int rows,
                            float* __restrict__ stats) {
    int c = threadIdx.x;  // 128
    float s = 0.f, q = 0.f;
    for (int r = blockIdx.x; r < rows; r += gridDim.x) {
        int a = atoms[r];
        float v = F[(size_t)r * 128 + c] + P[(size_t)a * 128 + c] +
                  R[(size_t)(r / G) * 128 + c];
        h[(size_t)r * 128 + c] = v;
        s += v;
        q += v * v;
    }
    atomicAdd(&stats[c], s);
    atomicAdd(&stats[128 + c], q);
}

__global__ void make_scaleshift(const float* __restrict__ stats,
                                const float* __restrict__ g,
                                const float* __restrict__ b,
                                float* __restrict__ scale,
                                float* __restrict__ shift, int C, float invM) {
    int j = blockIdx.x * blockDim.x + threadIdx.x;
    if (j >= C) return;
    float m = stats[j] * invM;
    float v = stats[128 + j] * invM - m * m;
    v = fmaxf(v, 0.f);
    float s = g[j] * rsqrtf(v + EPS);
    scale[j] = s;
    shift[j] = b[j] - m * s;
}

__global__ void bn_relu_out(const float* __restrict__ z,
                            const float* __restrict__ scale,
                            const float* __restrict__ shift,
                            float* __restrict__ out, size_t n, int C) {
    size_t idx = (size_t)blockIdx.x * blockDim.x + threadIdx.x;
    if (idx >= n) return;
    int c = (int)(idx % C);
    out[idx] = fmaxf(z[idx] * scale[c] + shift[c], 0.f);
}

// ---------------------------------------------------------------------------
// Host orchestration
// ---------------------------------------------------------------------------
static inline int cdiv(int a, int b) { return (a + b - 1) / b; }

static float* sym_addr(const void* s) {
    void* p = nullptr;
    cudaGetSymbolAddress(&p, s);
    return (float*)p;
}

// smem floats: 256 + 2*128*36 = 9472 -> 37888 B (under default limit)
static const int SMEM_G = (256 + 2 * 128 * 36) * 4;

extern "C" void kernel_launch(void* const* d_in, const int* in_sizes, int n_in,
                              void* d_out, int out_size) {
    const float* edge_feats = (const float*)d_in[0];
    const float* c5_feats = (const float*)d_in[1];
    const float* c6_feats = (const float*)d_in[2];
    const int* e_atoms = (const int*)d_in[3];
    const int* c5_atoms = (const int*)d_in[4];
    const int* c6_atoms = (const int*)d_in[5];
    const float* eW1 = (const float*)d_in[6];
    const float* eg1 = (const float*)d_in[7];
    const float* eb1 = (const float*)d_in[8];
    const float* eW2 = (const float*)d_in[9];
    const float* eg2 = (const float*)d_in[10];
    const float* eb2 = (const float*)d_in[11];
    const float* cW1 = (const float*)d_in[12];
    const float* cg1 = (const float*)d_in[13];
    const float* cb1 = (const float*)d_in[14];
    const float* cW2 = (const float*)d_in[15];
    const float* cg2 = (const float*)d_in[16];
    const float* cb2 = (const float*)d_in[17];

    float* out_edge = (float*)d_out;
    float* out_c5 = out_edge + (size_t)E_ROWS * H;
    float* out_c6 = out_c5 + (size_t)C5_ROWS * H;

    float* node64 = sym_addr(g_node64);
    float* cnt5 = node64 + NNODES * 64;
    float* cnt6 = node64 + NNODES * 65;
    float* b1_5 = sym_addr(g_b1_5);
    float* b1_6 = sym_addr(g_b1_6);
    float* n128_5 = sym_addr(g_n128_5);
    float* n128_6 = sym_addr(g_n128_6);
    float* b2_5 = sym_addr(g_b2_5);
    float* b2_6 = sym_addr(g_b2_6);
    float* nodeS = sym_addr(g_nodeS);
    float* Bt = sym_addr(g_B);
    float* Bm = sym_addr(g_Bm);
    float* P = sym_addr(g_P);
    float* R = sym_addr(g_R);
    float* F = sym_addr(g_F);
    float* h = sym_addr(g_h);
    float* z = sym_addr(g_z);
    float* wE1 = sym_addr(g_wE1);
    float* wE2 = sym_addr(g_wE2);
    float* wC1 = sym_addr(g_wC1);
    float* wC2 = sym_addr(g_wC2);
    float* stats = sym_addr(g_stats);
    float* sc1 = sym_addr(g_scale1);
    float* sh1 = sym_addr(g_shift1);
    float* sc2 = sym_addr(g_scale2);
    float* sh2 = sym_addr(g_shift2);

    const int TB = 256;

    // #1-3: weight permutation (fragment order + tf32 round)
    permute_w<<<cdiv(704 * 128, TB), TB>>>(eW1, wE1, 704, 128);
    permute_w<<<cdiv(320 * 128, TB), TB>>>(cW1, wC1, 320, 128);
    permute_w<<<cdiv(128 * 64, TB), TB>>>(eW2, wE2, 128, 64);
    // #4: edge F GEMM (profiled launch)
    gemm_mma<128, false, EPI_PLAIN><<<cdiv(E_ROWS, 128), 256, SMEM_G>>>(
        edge_feats, wE1, F, E_ROWS, 64, nullptr, nullptr, nullptr);
    // #5
    permute_w<<<cdiv(128 * 64, TB), TB>>>(cW2, wC2, 128, 64);

    // ---- scatter chain (fp32 exact) ----
    zero_kernel<<<cdiv(NNODES * 66, TB), TB>>>(node64, (size_t)NNODES * 66);
    scatter_add4<<<cdiv(E_ROWS * 16, TB), TB>>>(edge_feats, e_atoms, node64,
                                                E_ROWS, 64);
    count_atoms<<<cdiv(C5_ROWS, TB), TB>>>(c5_atoms, cnt5, C5_ROWS);
    count_atoms<<<cdiv(C6_ROWS, TB), TB>>>(c6_atoms, cnt6, C6_ROWS);

    bc_gather<5><<<cdiv(NC5 * 64, TB), TB>>>(node64, c5_atoms, b1_5, NC5, 64);
    bc_gather<6><<<cdiv(NC6 * 64, TB), TB>>>(node64, c6_atoms, b1_6, NC6, 64);

    init_node128<<<cdiv(NNODES * 64, TB), TB>>>(node64, cnt5, n128_5);
    init_node128<<<cdiv(NNODES * 64, TB), TB>>>(node64, cnt6, n128_6);
    scatter_grp4<5><<<cdiv(C5_ROWS * 16, TB), TB>>>(b1_5, c5_atoms, n128_5,
                                                    C5_ROWS, 64, 128, 64);
    scatter_grp4<6><<<cdiv(C6_ROWS * 16, TB), TB>>>(b1_6, c6_atoms, n128_6,
                                                    C6_ROWS, 64, 128, 64);

    bc_gather<5><<<cdiv(NC5 * 128, TB), TB>>>(n128_5, c5_atoms, b2_5, NC5, 128);
    bc_gather<6><<<cdiv(NC6 * 128, TB), TB>>>(n128_6, c6_atoms, b2_6, NC6, 128);

    init_nodeS<<<cdiv(NNODES * 320, TB), TB>>>(n128_5, n128_6, cnt5, cnt6,
                                               nodeS);
    scatter_grp4<5><<<cdiv(C5_ROWS * 32, TB), TB>>>(b2_5, c5_atoms, nodeS,
                                                    C5_ROWS, 128, 320, 128);
    scatter_grp4<6><<<cdiv(C6_ROWS * 32, TB), TB>>>(b2_6, c6_atoms, nodeS,
                                                    C6_ROWS, 128, 320, 128);
    scatter_grp4<1><<<cdiv(C5_ROWS * 16, TB), TB>>>(c5_feats, c5_atoms, nodeS,
                                                    C5_ROWS, 64, 320, 256);
    scatter_grp4<1><<<cdiv(C6_ROWS * 16, TB), TB>>>(c6_feats, c6_atoms, nodeS,
                                                    C6_ROWS, 64, 320, 256);

    // ================= EDGE MLP =================
    gemm_mma<128, false, EPI_PLAIN><<<cdiv(NNODES, 128), 256, SMEM_G>>>(
        nodeS, wE1 + 64 * 128, Bt, NNODES, 320, nullptr, nullptr, nullptr);
    gemm_mma<128, false, EPI_PLAIN><<<cdiv(NNODES, 128), 256, SMEM_G>>>(
        nodeS, wE1 + 384 * 128, Bm, NNODES, 320, nullptr, nullptr, nullptr);
    zero_kernel<<<1, 256>>>(stats, 256);
    compose_edge<<<2048, 128>>>(F, Bt, Bm, e_atoms, h, stats);
    make_scaleshift<<<1, 128>>>(stats, eg1, eb1, sc1, sh1, 128, 1.f / E_ROWS);
    zero_kernel<<<1, 256>>>(stats, 256);
    gemm_mma<64, true, EPI_STATS><<<cdiv(E_ROWS, 128), 256, SMEM_G>>>(
        h, wE2, z, E_ROWS, 128, sc1, sh1, stats);
    make_scaleshift<<<1, 64>>>(stats, eg2, eb2, sc2, sh2, 64, 1.f / E_ROWS);
    bn_relu_out<<<cdiv(E_ROWS * 64, TB), TB>>>(z, sc2, sh2, out_edge,
                                               (size_t)E_ROWS * 64, 64);

    // ================= CYCLE5 MLP =================
    gemm_mma<128, false, EPI_PLAIN><<<cdiv(C5_ROWS, 128), 256, SMEM_G>>>(
        c5_feats, wC1 + 256 * 128, F, C5_ROWS, 64, nullptr, nullptr, nullptr);
    gemm_mma<128, false, EPI_PLAIN><<<cdiv(NNODES, 128), 256, SMEM_G>>>(
        n128_5, wC1, P, NNODES, 128, nullptr, nullptr, nullptr);
    gemm_mma<128, false, EPI_PLAIN><<<cdiv(NC5, 128), 256, SMEM_G>>>(
        b2_5, wC1 + 128 * 128, R, NC5, 128, nullptr, nullptr, nullptr);
    zero_kernel<<<1, 256>>>(stats, 256);
    compose_cyc<5><<<2048, 128>>>(F, P, R, c5_atoms, h, C5_ROWS, stats);
    make_scaleshift<<<1, 128>>>(stats, cg1, cb1, sc1, sh1, 128, 1.f / C5_ROWS);
    zero_kernel<<<1, 256>>>(stats, 256);
    gemm_mma<64, true, EPI_STATS><<<cdiv(C5_ROWS, 128), 256, SMEM_G>>>(
        h, wC2, z, C5_ROWS, 128, sc1, sh1, stats);
    make_scaleshift<<<1, 64>>>(stats, cg2, cb2, sc2, sh2, 64, 1.f / C5_ROWS);
    bn_relu_out<<<cdiv(C5_ROWS * 64, TB), TB>>>(z, sc2, sh2, out_c5,
                                                (size_t)C5_ROWS * 64, 64);

    // ================= CYCLE6 MLP =================
    gemm_mma<128, false, EPI_PLAIN><<<cdiv(C6_ROWS, 128), 256, SMEM_G>>>(
        c6_feats, wC1 + 256 * 128, F, C6_ROWS, 64, nullptr, nullptr, nullptr);
    gemm_mma<128, false, EPI_PLAIN><<<cdiv(NNODES, 128), 256, SMEM_G>>>(
        n128_6, wC1, P, NNODES, 128, nullptr, nullptr, nullptr);
    gemm_mma<128, false, EPI_PLAIN><<<cdiv(NC6, 128), 256, SMEM_G>>>(
        b2_6, wC1 + 128 * 128, R, NC6, 128, nullptr, nullptr, nullptr);
    zero_kernel<<<1, 256>>>(stats, 256);
    compose_cyc<6><<<2048, 128>>>(F, P, R, c6_atoms, h, C6_ROWS, stats);
    make_scaleshift<<<1, 128>>>(stats, cg1, cb1, sc1, sh1, 128, 1.f / C6_ROWS);
    zero_kernel<<<1, 256>>>(stats, 256);
    gemm_mma<64, true, EPI_STATS><<<cdiv(C6_ROWS, 128), 256, SMEM_G>>>(
        h, wC2, z, C6_ROWS, 128, sc1, sh1, stats);
    make_scaleshift<<<1, 64>>>(stats, cg2, cb2, sc2, sh2, 64, 1.f / C6_ROWS);
    bn_relu_out<<<cdiv(C6_ROWS * 64, TB), TB>>>(z, sc2, sh2, out_c6,
                                                (size_t)C6_ROWS * 64, 64);

    (void)in_sizes;
    (void)n_in;
    (void)out_size;
}